// round 5
// baseline (speedup 1.0000x reference)
#include <cuda_runtime.h>
#include <cuda_fp16.h>
#include <cuda_bf16.h>

// Problem constants (fixed by the reference)
#define BB   2048
#define VV   2048
#define CC   512
#define MM   8
#define HH   16
#define EPSF 1e-6f
#define NBLK 148   // persistent: one block per SM

__device__ __forceinline__ float ex2_fast(float x) {
    float y;
    asm("ex2.approx.f32 %0, %1;" : "=f"(y) : "f"(x));
    return y;
}
__device__ __forceinline__ float rcp_fast(float x) {
    float y;
    asm("rcp.approx.f32 %0, %1;" : "=f"(y) : "f"(x));
    return y;
}
// NOTE: named *_fast to avoid colliding with cuda_fp16.hpp's h2tanh().
__device__ __forceinline__ __half2 h2tanh_fast(__half2 x) {
    unsigned xi = *reinterpret_cast<unsigned*>(&x), yi;
    asm("tanh.approx.f16x2 %0, %1;" : "=r"(yi) : "r"(xi));
    return *reinterpret_cast<__half2*>(&yi);
}

// Persistent kernel: 148 blocks, 512 threads (thread = channel c).
// Per-channel weights live in registers for the whole kernel. The MLP inner
// loop evaluates tanh in packed f16x2 (two m-values per lane), halving the
// MUFU issue count (the binding pipe). The W2 dot-product accumulates in f32
// to keep the only f16 error source the tanh argument rounding.
__global__ __launch_bounds__(CC, 1) void gradoptim_attn_kernel(
    const float* __restrict__ preds,
    const int*   __restrict__ mask_ids,
    const float* __restrict__ W1,   // (C, 2, H)
    const float* __restrict__ b1,   // (C, H)
    const float* __restrict__ W2,   // (C, H)
    const float* __restrict__ b2,   // (C,)
    float*       __restrict__ out)  // (B, V)
{
    __shared__ float row[2][VV];

    const int c = threadIdx.x;

    // ---- Per-channel weights: loaded exactly once per block ----
    float   w1a[HH];        // W1[c,0,h]  (f32: u = h_a*w1a + b1)
    __half2 w1bh[HH];       // W1[c,1,h]  broadcast to both half2 lanes
    float   w2s[HH];        // W2[c,h]    f32 for the accumulation
    float   b1v[HH];
    {
        const float4* W1p = reinterpret_cast<const float4*>(W1 + (size_t)c * 2 * HH);
        const float4* b1p = reinterpret_cast<const float4*>(b1 + (size_t)c * HH);
        const float4* W2p = reinterpret_cast<const float4*>(W2 + (size_t)c * HH);
        #pragma unroll
        for (int i = 0; i < 4; i++) {
            float4 a  = W1p[i];       // W1[c,0,4i..4i+3]
            float4 bq = W1p[4 + i];   // W1[c,1,4i..4i+3]
            float4 bv = b1p[i];
            float4 w2 = W2p[i];
            w1a[4*i+0] = a.x;  w1a[4*i+1] = a.y;  w1a[4*i+2] = a.z;  w1a[4*i+3] = a.w;
            b1v[4*i+0] = bv.x; b1v[4*i+1] = bv.y; b1v[4*i+2] = bv.z; b1v[4*i+3] = bv.w;
            w1bh[4*i+0] = __float2half2_rn(bq.x); w1bh[4*i+1] = __float2half2_rn(bq.y);
            w1bh[4*i+2] = __float2half2_rn(bq.z); w1bh[4*i+3] = __float2half2_rn(bq.w);
            w2s[4*i+0] = w2.x; w2s[4*i+1] = w2.y; w2s[4*i+2] = w2.z; w2s[4*i+3] = w2.w;
        }
    }
    const float b2c = b2[c];

    int idx[MM];
    {
        const int4* mi = reinterpret_cast<const int4*>(mask_ids + (size_t)c * MM);
        int4 i0 = mi[0], i1 = mi[1];
        idx[0] = i0.x; idx[1] = i0.y; idx[2] = i0.z; idx[3] = i0.w;
        idx[4] = i1.x; idx[5] = i1.y; idx[6] = i1.z; idx[7] = i1.w;
    }

    const float LOG2E = 1.4426950408889634f;

    int b = blockIdx.x;
    int buf = 0;
    float4 v4;
    if (b < BB) v4 = reinterpret_cast<const float4*>(preds + (size_t)b * VV)[c];

    while (b < BB) {
        // Stage current row into smem; copy untouched tail columns verbatim.
        reinterpret_cast<float4*>(row[buf])[c] = v4;
        if (c >= CC / 4)
            reinterpret_cast<float4*>(out + (size_t)b * VV)[c] = v4;
        __syncthreads();

        // Prefetch next row so LDG latency hides under compute.
        const int bn = b + NBLK;
        if (bn < BB) v4 = reinterpret_cast<const float4*>(preds + (size_t)bn * VV)[c];

        // ---- Compute ----
        const float h_a = row[buf][c];
        float hm[MM];
        #pragma unroll
        for (int m = 0; m < MM; m++) hm[m] = row[buf][idx[m]];

        // u[h] = h_a*W1[c,0,h] + b1[c,h] in f32, broadcast to half2.
        __half2 uh[HH];
        #pragma unroll
        for (int h = 0; h < HH; h++)
            uh[h] = __float2half2_rn(fmaf(h_a, w1a[h], b1v[h]));

        // Scores: two m-values per half2 lane; tanh packed, accumulate f32.
        float sc[MM];
        #pragma unroll
        for (int p = 0; p < MM / 2; p++) {
            __half2 x2 = __floats2half2_rn(hm[2*p], hm[2*p + 1]);
            float s0 = b2c, s1 = b2c;
            #pragma unroll
            for (int h = 0; h < HH; h++) {
                __half2 t = h2tanh_fast(__hfma2(x2, w1bh[h], uh[h]));
                float2 tf = __half22float2(t);
                s0 = fmaf(w2s[h], tf.x, s0);
                s1 = fmaf(w2s[h], tf.y, s1);
            }
            sc[2*p]     = s0;
            sc[2*p + 1] = s1;
        }

        // Softmax over m; weighted sum of h_m in full f32.
        float mx = sc[0];
        #pragma unroll
        for (int m = 1; m < MM; m++) mx = fmaxf(mx, sc[m]);

        float sum = 0.0f, ws = 0.0f;
        #pragma unroll
        for (int m = 0; m < MM; m++) {
            float e = ex2_fast((sc[m] - mx) * LOG2E);
            sum = sum + e;
            ws  = fmaf(e, hm[m], ws);
        }
        const float weighted  = ws * rcp_fast(sum);
        const float corrected = fmaxf(h_a, weighted + EPSF);

        out[(size_t)b * VV + c] = corrected;

        buf ^= 1;
        b = bn;
    }
}

extern "C" void kernel_launch(void* const* d_in, const int* in_sizes, int n_in,
                              void* d_out, int out_size) {
    (void)in_sizes; (void)n_in; (void)out_size;
    const float* preds    = (const float*)d_in[0];
    // d_in[1] = ground_truth (unused by the reference)
    const int*   mask_ids = (const int*)  d_in[2];
    const float* W1       = (const float*)d_in[3];
    const float* b1       = (const float*)d_in[4];
    const float* W2       = (const float*)d_in[5];
    const float* b2       = (const float*)d_in[6];
    float*       out      = (float*)d_out;

    gradoptim_attn_kernel<<<NBLK, CC>>>(preds, mask_ids, W1, b1, W2, b2, out);
}